// round 12
// baseline (speedup 1.0000x reference)
#include <cuda_runtime.h>
#include <math.h>

#define BATCH   256
#define D_INNER 5120
#define DT_RANK 160
#define NSTATE  16
#define NCOLS   192           // 160 (W_delta) + 16 (W_B) + 16 (W_C)

#define MT    32              // batch tile (gemm1)
#define KC1   64              // K chunk for gemm1
#define NKC   (D_INNER / KC1) // 80
#define NMT   (BATCH / MT)    // 8

#define DT_MT 16              // m-tile for k_dt
#define DT_NT 128             // d-tile for k_dt

typedef unsigned long long u64;

// packed f32x2 helpers -------------------------------------------------------
__device__ __forceinline__ u64 pfma(u64 a, u64 b, u64 c) {
    u64 d;
    asm("fma.rn.f32x2 %0, %1, %2, %3;" : "=l"(d) : "l"(a), "l"(b), "l"(c));
    return d;
}
__device__ __forceinline__ u64 pk(float lo, float hi) {
    u64 r;
    asm("mov.b64 %0, {%1, %2};" : "=l"(r) : "f"(lo), "f"(hi));
    return r;
}
__device__ __forceinline__ float2 upk(u64 p) {
    float2 v;
    asm("mov.b64 {%0, %1}, %2;" : "=f"(v.x), "=f"(v.y) : "l"(p));
    return v;
}

// Scratch (allocation-free rule: __device__ globals)
__device__ float g_part[NKC * BATCH * NCOLS];   // 15.7 MB partials
__device__ float g_T  [BATCH * DT_RANK];
__device__ float g_Bp [BATCH * NSTATE];
__device__ float g_C  [BATCH * NSTATE];
__device__ float g_A  [D_INNER * NSTATE];       // -exp(A_log)
__device__ float g_dt [BATCH * D_INNER];        // softplus output

// ---------------------------------------------------------------------------
// Kernel 1: partial GEMM  P = x[mtile, kchunk] @ [W_delta | W_B | W_C]
// grid (8, 80), block 192 (thread = output column). Packed over even/odd k.
// ---------------------------------------------------------------------------
__global__ __launch_bounds__(192)
void k_gemm1(const float* __restrict__ x,
             const float* __restrict__ Wd,
             const float* __restrict__ Wb,
             const float* __restrict__ Wc)
{
    __shared__ __align__(16) float xs[MT * KC1];   // 8 KB, m-major
    const int m0  = blockIdx.x * MT;
    const int k0  = blockIdx.y * KC1;
    const int tid = threadIdx.x;

    for (int i = tid; i < MT * (KC1 / 4); i += 192)
        ((float4*)xs)[i] =
            *(const float4*)(x + (size_t)(m0 + i / (KC1 / 4)) * D_INNER
                               + k0 + (i % (KC1 / 4)) * 4);
    __syncthreads();

    const float* wptr;
    int wstride;
    if (tid < DT_RANK) {
        wptr = Wd + (size_t)k0 * DT_RANK + tid;                wstride = DT_RANK;
    } else if (tid < DT_RANK + NSTATE) {
        wptr = Wb + (size_t)k0 * NSTATE + (tid - DT_RANK);     wstride = NSTATE;
    } else {
        wptr = Wc + (size_t)k0 * NSTATE + (tid - DT_RANK - NSTATE); wstride = NSTATE;
    }

    u64 acc[MT];   // lane0: even-k partial, lane1: odd-k partial
    #pragma unroll
    for (int m = 0; m < MT; m++) acc[m] = 0ull;

    float w0 = wptr[0], w1 = wptr[wstride], w2 = wptr[2 * wstride], w3 = wptr[3 * wstride];

    #pragma unroll 2
    for (int k = 0; k < KC1; k += 4) {
        const float* wn = wptr + 4 * wstride;
        float n0 = w0, n1 = w1, n2 = w2, n3 = w3;
        if (k + 4 < KC1) {
            n0 = wn[0]; n1 = wn[wstride]; n2 = wn[2 * wstride]; n3 = wn[3 * wstride];
        }
        const u64 wp01 = pk(w0, w1);
        const u64 wp23 = pk(w2, w3);
        const ulonglong2* xrow = (const ulonglong2*)(xs + k);
        #pragma unroll
        for (int m = 0; m < MT; m++) {
            // row stride = KC1 floats = KC1/4 ulonglong2 (16B) units
            ulonglong2 xv = xrow[m * (KC1 / 4)];   // 16B: k..k+3
            acc[m] = pfma(xv.x, wp01, acc[m]);
            acc[m] = pfma(xv.y, wp23, acc[m]);
        }
        w0 = n0; w1 = n1; w2 = n2; w3 = n3; wptr = wn;
    }

    float* pout = g_part + ((size_t)blockIdx.y * BATCH + m0) * NCOLS + tid;
    #pragma unroll
    for (int m = 0; m < MT; m++) {
        float2 v = upk(acc[m]);
        pout[(size_t)m * NCOLS] = v.x + v.y;
    }
}

// ---------------------------------------------------------------------------
// Kernel 2: reduce 80 K-chunk partials -> T / Bp / C
// ---------------------------------------------------------------------------
__global__ __launch_bounds__(256)
void k_reduce()
{
    int idx = blockIdx.x * 256 + threadIdx.x;
    if (idx >= BATCH * NCOLS) return;
    int row = idx / NCOLS;
    int n   = idx % NCOLS;
    float s = 0.f;
    #pragma unroll
    for (int c = 0; c < NKC; c++)
        s += g_part[((size_t)c * BATCH + row) * NCOLS + n];
    if (n < DT_RANK)               g_T [row * DT_RANK + n] = s;
    else if (n < DT_RANK + NSTATE) g_Bp[row * NSTATE + (n - DT_RANK)] = s;
    else                           g_C [row * NSTATE + (n - DT_RANK - NSTATE)] = s;
}

// ---------------------------------------------------------------------------
// Kernel 3: A = -exp(A_log)
// ---------------------------------------------------------------------------
__global__ __launch_bounds__(256)
void k_prep(const float* __restrict__ A_log)
{
    int idx = blockIdx.x * 256 + threadIdx.x;
    if (idx < D_INNER * NSTATE) g_A[idx] = -__expf(A_log[idx]);
}

// ---------------------------------------------------------------------------
// Kernel 4: dt = softplus(T @ W_dt + b_dt)
// grid (16, 40), block 256. Thread tile 2m x 4n (packed over n-pairs).
// T staged as duplicated f32x2 pairs; W_dt double-buffered.
// ---------------------------------------------------------------------------
__global__ __launch_bounds__(256)
void k_dt(const float* __restrict__ Wdt, const float* __restrict__ b_dt)
{
    __shared__ __align__(16) u64   Tsd[DT_MT * DT_RANK];      // 20 KB (dup pairs)
    __shared__ __align__(16) float ws[2][32 * DT_NT];         // 2 x 16 KB
    const int m0  = blockIdx.x * DT_MT;
    const int d0  = blockIdx.y * DT_NT;
    const int tid = threadIdx.x;
    const int mg  = tid >> 5;          // 0..7 -> rows 2mg, 2mg+1
    const int ng  = tid & 31;          // cols 4ng .. 4ng+3

    // stage T as duplicated pairs
    for (int i = tid; i < DT_MT * DT_RANK; i += 256) {
        float v = g_T[(size_t)m0 * DT_RANK + i];
        Tsd[i] = pk(v, v);
    }
    // preload W chunk 0
    for (int i = tid; i < 32 * (DT_NT / 4); i += 256)
        ((float4*)ws[0])[i] =
            *(const float4*)(Wdt + (size_t)(i / (DT_NT / 4)) * D_INNER
                                 + d0 + (i % (DT_NT / 4)) * 4);
    __syncthreads();

    u64 acc00 = 0ull, acc01 = 0ull, acc10 = 0ull, acc11 = 0ull;

    #pragma unroll
    for (int kc = 0; kc < DT_RANK / 32; kc++) {
        const int buf = kc & 1;
        // prefetch next chunk into the other buffer
        if (kc + 1 < DT_RANK / 32) {
            for (int i = tid; i < 32 * (DT_NT / 4); i += 256)
                ((float4*)ws[buf ^ 1])[i] =
                    *(const float4*)(Wdt + (size_t)((kc + 1) * 32 + i / (DT_NT / 4)) * D_INNER
                                         + d0 + (i % (DT_NT / 4)) * 4);
        }
        const u64*        trow0 = Tsd + (2 * mg + 0) * DT_RANK + kc * 32;
        const u64*        trow1 = Tsd + (2 * mg + 1) * DT_RANK + kc * 32;
        const ulonglong2* wrow  = (const ulonglong2*)ws[buf] + ng;
        #pragma unroll
        for (int k = 0; k < 32; k++) {
            u64 t0 = trow0[k];
            u64 t1 = trow1[k];
            // row stride = DT_NT floats = DT_NT/4 ulonglong2 (16B) units
            ulonglong2 wv = wrow[k * (DT_NT / 4)];
            acc00 = pfma(t0, wv.x, acc00);
            acc01 = pfma(t0, wv.y, acc01);
            acc10 = pfma(t1, wv.x, acc10);
            acc11 = pfma(t1, wv.y, acc11);
        }
        __syncthreads();
    }

    const float4 bd = *(const float4*)(b_dt + d0 + ng * 4);
    float2 a0 = upk(acc00), a1 = upk(acc01), a2 = upk(acc10), a3 = upk(acc11);

    float4 z0, z1;
    z0.x = a0.x + bd.x; z0.y = a0.y + bd.y; z0.z = a1.x + bd.z; z0.w = a1.y + bd.w;
    z1.x = a2.x + bd.x; z1.y = a2.y + bd.y; z1.z = a3.x + bd.z; z1.w = a3.y + bd.w;

    z0.x = (z0.x > 20.f) ? z0.x : log1pf(__expf(z0.x));
    z0.y = (z0.y > 20.f) ? z0.y : log1pf(__expf(z0.y));
    z0.z = (z0.z > 20.f) ? z0.z : log1pf(__expf(z0.z));
    z0.w = (z0.w > 20.f) ? z0.w : log1pf(__expf(z0.w));
    z1.x = (z1.x > 20.f) ? z1.x : log1pf(__expf(z1.x));
    z1.y = (z1.y > 20.f) ? z1.y : log1pf(__expf(z1.y));
    z1.z = (z1.z > 20.f) ? z1.z : log1pf(__expf(z1.z));
    z1.w = (z1.w > 20.f) ? z1.w : log1pf(__expf(z1.w));

    *(float4*)(g_dt + (size_t)(m0 + 2 * mg + 0) * D_INNER + d0 + ng * 4) = z0;
    *(float4*)(g_dt + (size_t)(m0 + 2 * mg + 1) * D_INNER + d0 + ng * 4) = z1;
}

// ---------------------------------------------------------------------------
// Kernel 5: streaming epilogue. grid (8, 160), block 256.
// Block tile: 32 batches x 32 d. Thread: fixed d, 4 batches.
// ---------------------------------------------------------------------------
__global__ __launch_bounds__(256)
void k_epi(const float* __restrict__ x,
           const float* __restrict__ h,
           const float* __restrict__ Dv,
           float* __restrict__ out)
{
    __shared__ float Bsh[32 * NSTATE];
    __shared__ float Csh[32 * NSTATE];
    const int b0  = blockIdx.x * 32;
    const int d0  = blockIdx.y * 32;
    const int tid = threadIdx.x;
    const int dl  = tid & 31;
    const int bg  = tid >> 5;

    for (int i = tid; i < 32 * NSTATE; i += 256) {
        Bsh[i] = g_Bp[b0 * NSTATE + i];
        Csh[i] = g_C [b0 * NSTATE + i];
    }
    __syncthreads();

    const int d = d0 + dl;
    float a[NSTATE];
    #pragma unroll
    for (int q = 0; q < 4; q++) {
        float4 av = *(const float4*)(g_A + (size_t)d * NSTATE + q * 4);
        a[q * 4 + 0] = av.x; a[q * 4 + 1] = av.y;
        a[q * 4 + 2] = av.z; a[q * 4 + 3] = av.w;
    }
    const float Dd = Dv[d];

    #pragma unroll
    for (int i = 0; i < 4; i++) {
        const int b = b0 + bg * 4 + i;
        const size_t off = (size_t)b * D_INNER + d;
        const float dt  = g_dt[off];
        const float xv  = x[off];
        const float dtx = dt * xv;
        const float4* hp = (const float4*)(h + off * NSTATE);
        const int bb = (bg * 4 + i) * NSTATE;
        float y = 0.f;
        #pragma unroll
        for (int q = 0; q < 4; q++) {
            float4 h4 = hp[q];
            float hn;
            hn = fmaf(__expf(dt * a[q*4+0]), h4.x, dtx * Bsh[bb + q*4+0]); y = fmaf(hn, Csh[bb + q*4+0], y);
            hn = fmaf(__expf(dt * a[q*4+1]), h4.y, dtx * Bsh[bb + q*4+1]); y = fmaf(hn, Csh[bb + q*4+1], y);
            hn = fmaf(__expf(dt * a[q*4+2]), h4.z, dtx * Bsh[bb + q*4+2]); y = fmaf(hn, Csh[bb + q*4+2], y);
            hn = fmaf(__expf(dt * a[q*4+3]), h4.w, dtx * Bsh[bb + q*4+3]); y = fmaf(hn, Csh[bb + q*4+3], y);
        }
        out[off] = fmaf(xv, Dd, y);
    }
}

// ---------------------------------------------------------------------------
// Inputs (metadata order): x, h, W_delta, W_dt, b_dt, A_log, W_B, W_C, D
// ---------------------------------------------------------------------------
extern "C" void kernel_launch(void* const* d_in, const int* in_sizes, int n_in,
                              void* d_out, int out_size)
{
    const float* x      = (const float*)d_in[0];
    const float* h      = (const float*)d_in[1];
    const float* Wdelta = (const float*)d_in[2];
    const float* Wdt    = (const float*)d_in[3];
    const float* bdt    = (const float*)d_in[4];
    const float* Alog   = (const float*)d_in[5];
    const float* WB     = (const float*)d_in[6];
    const float* WC     = (const float*)d_in[7];
    const float* Dv     = (const float*)d_in[8];
    float* out = (float*)d_out;

    k_gemm1<<<dim3(NMT, NKC), 192>>>(x, Wdelta, WB, WC);
    k_prep<<<(D_INNER * NSTATE + 255) / 256, 256>>>(Alog);
    k_reduce<<<(BATCH * NCOLS + 255) / 256, 256>>>();
    k_dt<<<dim3(BATCH / DT_MT, D_INNER / DT_NT), 256>>>(Wdt, bdt);
    k_epi<<<dim3(BATCH / 32, D_INNER / 32), 256>>>(x, h, Dv, out);
}